// round 17
// baseline (speedup 1.0000x reference)
#include <cuda_runtime.h>
#include <cuda_fp16.h>
#include <math.h>
#include <stdint.h>

#define BB 32
#define CC 256
#define NN 3136
#define OUTC 32896            // 256*257/2
#define MATSZ (BB*CC*CC)
#define XSZ (BB*CC*NN)

#define CHK 32
#define STG64 16384           // 64x64 stage: A(8K)+B(8K)
#define SMEM64 (3*STG64)      // 49152
#define SSCALE 64.0f
#define INVS2 (1.0f/(SSCALE*SSCALE))
#define MP 72                 // transpose-buffer pitch in halves

// 64x64 tiling: 10 upper tiles of 4x4 blocks
__device__ __constant__ int c_TI[10] = {0,0,0,0,1,1,1,2,2,3};
__device__ __constant__ int c_TJ[10] = {0,1,2,3,1,2,3,2,3,3};

// ---------------- scratch: matrices stored as hi/lo fp16 pairs ----------------
// slot usage documented in kernel_launch
__device__ __align__(16) __half g_H[7*MATSZ];
__device__ __align__(16) __half g_L[7*MATSZ];
__device__ __align__(16) __half g_Xh[XSZ];
__device__ __align__(16) __half g_Xl[XSZ];
__device__ float g_s[BB*CC];
__device__ float g_q[BB*CC];
__device__ float g_tr[BB];

// ---------------- primitives ----------------
__device__ __forceinline__ uint32_t smem_u32(const void* p) {
    uint32_t a;
    asm("{ .reg .u64 t; cvta.to.shared.u64 t, %1; cvt.u32.u64 %0, t; }" : "=r"(a) : "l"(p));
    return a;
}

__device__ __forceinline__ void mma16(float* c, const unsigned* a, const unsigned* b) {
    asm volatile(
        "mma.sync.aligned.m16n8k16.row.col.f32.f16.f16.f32 "
        "{%0,%1,%2,%3}, {%4,%5,%6,%7}, {%8,%9}, {%0,%1,%2,%3};"
        : "+f"(c[0]), "+f"(c[1]), "+f"(c[2]), "+f"(c[3])
        : "r"(a[0]), "r"(a[1]), "r"(a[2]), "r"(a[3]), "r"(b[0]), "r"(b[1]));
}

__device__ __forceinline__ void ldm4(unsigned r[4], uint32_t a) {
    asm volatile("ldmatrix.sync.aligned.m8n8.x4.shared.b16 {%0,%1,%2,%3}, [%4];"
                 : "=r"(r[0]), "=r"(r[1]), "=r"(r[2]), "=r"(r[3]) : "r"(a));
}

#define CP16(dst, src) \
    asm volatile("cp.async.cg.shared.global [%0], [%1], 16;" :: "r"(dst), "l"(src))
#define CP_COMMIT() asm volatile("cp.async.commit_group;" ::: "memory")
#define CP_WAIT1() asm volatile("cp.async.wait_group 1;" ::: "memory")

__device__ __forceinline__ void split_pair(float v0, float v1, unsigned& hi, unsigned& lo) {
    float s0 = v0 * SSCALE, s1 = v1 * SSCALE;
    __half h0 = __float2half_rn(s0), h1 = __float2half_rn(s1);
    __half l0 = __float2half_rn(s0 - __half2float(h0));
    __half l1 = __float2half_rn(s1 - __half2float(h1));
    __half2 hh = __halves2half2(h0, h1), ll = __halves2half2(l0, l1);
    hi = *(unsigned*)&hh;
    lo = *(unsigned*)&ll;
}

// ================= 64x64 mainloop (shared by gram + all NS GEMMs) =================
__device__ __forceinline__ void issue_chunk64(uint32_t dstBase,
                                              const __half* Ah, const __half* Al,
                                              const __half* Bh, const __half* Bl,
                                              int strideH, int k0, int tid) {
#pragma unroll
    for (int i = 0; i < 8; ++i) {
        int n = i * 128 + tid;
        int mat = n >> 9;
        int m = n & 511;
        int row = m >> 3, g = m & 7;
        const __half* hbase = (mat == 0) ? (g < 4 ? Ah : Al) : (g < 4 ? Bh : Bl);
        const __half* src = hbase + (size_t)row * strideH + k0 + 8 * (g & 3);
        uint32_t dst = dstBase + mat * 8192 + row * 128 + ((g ^ (row & 7)) << 4);
        CP16(dst, src);
    }
}

__device__ __forceinline__ void compute_chunk64(uint32_t stBase, float acc[2][4][4],
                                                int wm, int wn, int lane) {
    int lr = lane & 7;
    int lt8 = (lane >> 3) & 1;
    int lkh = (lane >> 4) & 1;
    uint32_t aL = stBase + (wm * 32 + lt8 * 8 + lr) * 128;
    uint32_t bL = stBase + 8192 + (wn * 32 + lkh * 8 + lr) * 128;
#pragma unroll
    for (int ks = 0; ks < 2; ++ks) {
        unsigned ah[2][4], al[2][4], bh[2][4], bl[2][4];
        int gA = ks * 2 + lkh, gB = ks * 2 + lt8;
        ldm4(ah[0], aL + ((gA ^ lr) << 4));
        ldm4(ah[1], aL + 2048 + ((gA ^ lr) << 4));
        ldm4(al[0], aL + (((gA + 4) ^ lr) << 4));
        ldm4(al[1], aL + 2048 + (((gA + 4) ^ lr) << 4));
        ldm4(bh[0], bL + ((gB ^ lr) << 4));
        ldm4(bh[1], bL + 2048 + ((gB ^ lr) << 4));
        ldm4(bl[0], bL + (((gB + 4) ^ lr) << 4));
        ldm4(bl[1], bL + 2048 + (((gB + 4) ^ lr) << 4));
#pragma unroll
        for (int it = 0; it < 2; ++it)
#pragma unroll
            for (int jt = 0; jt < 4; ++jt)
                mma16(acc[it][jt], ah[it], &bh[jt >> 1][(jt & 1) * 2]);
#pragma unroll
        for (int it = 0; it < 2; ++it)
#pragma unroll
            for (int jt = 0; jt < 4; ++jt)
                mma16(acc[it][jt], ah[it], &bl[jt >> 1][(jt & 1) * 2]);
#pragma unroll
        for (int it = 0; it < 2; ++it)
#pragma unroll
            for (int jt = 0; jt < 4; ++jt)
                mma16(acc[it][jt], al[it], &bh[jt >> 1][(jt & 1) * 2]);
    }
}

__device__ __forceinline__ void run_loop64(uint32_t smem_u,
                                           const __half* Ah, const __half* Al,
                                           const __half* Bh, const __half* Bl,
                                           int strideH, int nch, float acc[2][4][4],
                                           int wm, int wn, int lane, int tid) {
    issue_chunk64(smem_u, Ah, Al, Bh, Bl, strideH, 0, tid);
    CP_COMMIT();
    issue_chunk64(smem_u + STG64, Ah, Al, Bh, Bl, strideH, CHK, tid);
    CP_COMMIT();
    int st = 0;
    for (int s = 0; s < nch; ++s) {
        CP_WAIT1();
        __syncthreads();
        if (s + 2 < nch) {
            int st2 = st + 2;
            if (st2 >= 3) st2 -= 3;
            issue_chunk64(smem_u + st2 * STG64, Ah, Al, Bh, Bl, strideH, (s + 2) * CHK, tid);
        }
        CP_COMMIT();
        compute_chunk64(smem_u + st * STG64, acc, wm, wn, lane);
        if (++st == 3) st = 0;
    }
}

// ---------------- splitx + trace ----------------
__global__ __launch_bounds__(256) void splitx_kernel(const float* __restrict__ X,
                                                     __half* __restrict__ Xh,
                                                     __half* __restrict__ Xl,
                                                     float* __restrict__ s,
                                                     float* __restrict__ q) {
    int c = blockIdx.x, b = blockIdx.y;
    size_t base = ((size_t)b * CC + c) * NN;
    const float4* row = (const float4*)(X + base);
    float acc = 0.f, accq = 0.f;
    for (int i = threadIdx.x; i < NN / 4; i += 256) {
        float4 v = row[i];
        acc += v.x + v.y + v.z + v.w;
        accq += v.x * v.x + v.y * v.y + v.z * v.z + v.w * v.w;
        unsigned h0, l0, h1, l1;
        split_pair(v.x, v.y, h0, l0);
        split_pair(v.z, v.w, h1, l1);
        *(uint2*)(Xh + base + i * 4) = make_uint2(h0, h1);
        *(uint2*)(Xl + base + i * 4) = make_uint2(l0, l1);
    }
    __shared__ float ss[256], sq[256];
    ss[threadIdx.x] = acc;
    sq[threadIdx.x] = accq;
    __syncthreads();
    for (int st = 128; st > 0; st >>= 1) {
        if (threadIdx.x < st) {
            ss[threadIdx.x] += ss[threadIdx.x + st];
            sq[threadIdx.x] += sq[threadIdx.x + st];
        }
        __syncthreads();
    }
    if (threadIdx.x == 0) {
        s[b * CC + c] = ss[0];
        q[b * CC + c] = sq[0];
    }
}

__global__ __launch_bounds__(256) void trred_kernel(const float* __restrict__ s,
                                                    const float* __restrict__ q,
                                                    float* __restrict__ tr) {
    int b = blockIdx.x, c = threadIdx.x;
    const float inv_n = 1.0f / (float)NN;
    const float inv_n2 = inv_n * inv_n;
    float sv = s[b * CC + c];
    float v = q[b * CC + c] * inv_n - sv * sv * inv_n2;
    __shared__ float sm[256];
    sm[c] = v;
    __syncthreads();
    for (int st = 128; st > 0; st >>= 1) {
        if (c < st) sm[c] += sm[c + st];
        __syncthreads();
    }
    if (c == 0) tr[b] = sm[0];
}

// ---------------- gram: a = (XX^T/n - ss^T/n^2)/tr only ----------------
__global__ __launch_bounds__(128, 4) void gram_mma(const __half* __restrict__ Xh,
                                                   const __half* __restrict__ Xl,
                                                   const float* __restrict__ sv,
                                                   const float* __restrict__ trv,
                                                   __half* __restrict__ H,
                                                   __half* __restrict__ L) {
    extern __shared__ unsigned swm[];
    uint32_t smem_u = smem_u32(swm);
    int b = blockIdx.z, tile = blockIdx.x;
    int i0 = c_TI[tile] * 64, j0 = c_TJ[tile] * 64;
    bool mirror = (i0 != j0);
    int tid = threadIdx.x;
    int warp = tid >> 5, lane = tid & 31;
    int wm = warp >> 1, wn = warp & 1, g = lane >> 2, t = lane & 3;
    float acc[2][4][4] = {};

    const __half* Xhb = Xh + (size_t)b * CC * NN;
    const __half* Xlb = Xl + (size_t)b * CC * NN;
    run_loop64(smem_u, Xhb + (size_t)i0 * NN, Xlb + (size_t)i0 * NN,
               Xhb + (size_t)j0 * NN, Xlb + (size_t)j0 * NN, NN, NN / CHK,
               acc, wm, wn, lane, tid);

    __syncthreads();
    __half* M = (__half*)swm;        // transpose buffer [2][64][MP]

    const float inv_n = 1.0f / (float)NN;
    const float inv_n2 = inv_n * inv_n;
    float invtr = 1.0f / trv[b];
    float c1 = INVS2 * inv_n * invtr;
    float c2 = inv_n2 * invtr;
    __half* Ah = H + (size_t)b * CC * CC;
    __half* Al = L + (size_t)b * CC * CC;
#pragma unroll
    for (int it = 0; it < 2; ++it)
#pragma unroll
        for (int jt = 0; jt < 4; ++jt) {
            int gi = i0 + wm * 32 + it * 16 + g;
            int gj = j0 + wn * 32 + jt * 8 + 2 * t;
            float* ca = acc[it][jt];
#pragma unroll
            for (int h = 0; h < 2; ++h) {
                int r = gi + h * 8;
                float si = sv[b * CC + r];
                float a0 = ca[h * 2 + 0] * c1 - si * sv[b * CC + gj] * c2;
                float a1 = ca[h * 2 + 1] * c1 - si * sv[b * CC + gj + 1] * c2;
                unsigned hiA, loA;
                split_pair(a0, a1, hiA, loA);
                *(unsigned*)&Ah[(size_t)r * CC + gj] = hiA;
                *(unsigned*)&Al[(size_t)r * CC + gj] = loA;
                if (mirror) {
                    int r_l = r - i0, c_l = gj - j0;
                    __half2 x = *(__half2*)&hiA;
                    M[(0 * 64 + c_l) * MP + r_l] = __low2half(x);
                    M[(0 * 64 + c_l + 1) * MP + r_l] = __high2half(x);
                    x = *(__half2*)&loA;
                    M[(1 * 64 + c_l) * MP + r_l] = __low2half(x);
                    M[(1 * 64 + c_l + 1) * MP + r_l] = __high2half(x);
                }
            }
        }
    if (mirror) {
        __syncthreads();
        int comp = tid >> 6, c_l = tid & 63;
        const uint4* srcv = (const uint4*)(M + (comp * 64 + c_l) * MP);
        __half* dstp = (comp ? Al : Ah) + (size_t)(j0 + c_l) * CC + i0;
        uint4* dstv = (uint4*)dstp;
#pragma unroll
        for (int w2 = 0; w2 < 8; ++w2) dstv[w2] = srcv[w2];
    }
}

// ---------------- NS pair GEMM: 64x64 tiles, EPI0, two jobs via grid.y ----------------
__global__ __launch_bounds__(128, 4) void ns_pair(__half* __restrict__ H,
                                                  __half* __restrict__ L,
                                                  int p0, int q0, int cs0,
                                                  int p1, int q1, int cs1) {
    extern __shared__ unsigned swm[];
    uint32_t smem_u = smem_u32(swm);
    int b = blockIdx.z, tile = blockIdx.x;
    int sel = blockIdx.y;
    int ps = sel ? p1 : p0, qs = sel ? q1 : q0, cs = sel ? cs1 : cs0;
    int i0 = c_TI[tile] * 64, j0 = c_TJ[tile] * 64;
    bool mirror = (i0 != j0);
    int tid = threadIdx.x;
    int warp = tid >> 5, lane = tid & 31;
    int wm = warp >> 1, wn = warp & 1, g = lane >> 2, t = lane & 3;
    float acc[2][4][4] = {};

    size_t mb = (size_t)b * CC * CC;
    run_loop64(smem_u,
               H + (size_t)ps * MATSZ + mb + (size_t)i0 * CC,
               L + (size_t)ps * MATSZ + mb + (size_t)i0 * CC,
               H + (size_t)qs * MATSZ + mb + (size_t)j0 * CC,
               L + (size_t)qs * MATSZ + mb + (size_t)j0 * CC,
               CC, CC / CHK, acc, wm, wn, lane, tid);

    __syncthreads();
    __half* M = (__half*)swm;
    __half* Ch = H + (size_t)cs * MATSZ + mb;
    __half* Cl = L + (size_t)cs * MATSZ + mb;
#pragma unroll
    for (int it = 0; it < 2; ++it)
#pragma unroll
        for (int jt = 0; jt < 4; ++jt) {
            int gi = i0 + wm * 32 + it * 16 + g;
            int gj = j0 + wn * 32 + jt * 8 + 2 * t;
            float* ca = acc[it][jt];
#pragma unroll
            for (int h = 0; h < 2; ++h) {
                int r = gi + h * 8;
                float v0 = ca[h * 2 + 0] * INVS2, v1 = ca[h * 2 + 1] * INVS2;
                unsigned hi, lo;
                split_pair(v0, v1, hi, lo);
                *(unsigned*)&Ch[(size_t)r * CC + gj] = hi;
                *(unsigned*)&Cl[(size_t)r * CC + gj] = lo;
                if (mirror) {
                    int r_l = r - i0, c_l = gj - j0;
                    __half2 x = *(__half2*)&hi;
                    M[(0 * 64 + c_l) * MP + r_l] = __low2half(x);
                    M[(0 * 64 + c_l + 1) * MP + r_l] = __high2half(x);
                    x = *(__half2*)&lo;
                    M[(1 * 64 + c_l) * MP + r_l] = __low2half(x);
                    M[(1 * 64 + c_l + 1) * MP + r_l] = __high2half(x);
                }
            }
        }
    if (mirror) {
        __syncthreads();
        int comp = tid >> 6, c_l = tid & 63;
        const uint4* srcv = (const uint4*)(M + (comp * 64 + c_l) * MP);
        __half* dstp = (comp ? Cl : Ch) + (size_t)(j0 + c_l) * CC + i0;
        uint4* dstv = (uint4*)dstp;
#pragma unroll
        for (int w2 = 0; w2 < 8; ++w2) dstv[w2] = srcv[w2];
    }
}

// ---------------- NS 64x64 single GEMM with polynomial epilogues ----------------
// EPI 0: C1 = P@Q
// EPI 2: triuvec(P@Q * sqrt(tr))
// EPI 3: A2 = P@Q(=a^2); C1 = 0.25*A2 - 1.5*a + 2.25*I ; C2 = 1.5*a - 0.5*A2   (us = a)
// EPI 4: W = P@Q(=u^2); C1 = W ; C2 = 0.0625*W - 0.5625*u + 1.6875*I           (us = u)
// EPI 5: S = P@Q(=R*W); C1 = S - 2.4375*u + 2.25*I                             (us = u)
template <int EPI>
__global__ __launch_bounds__(128, 4) void ns64(__half* __restrict__ H,
                                               __half* __restrict__ L,
                                               int ps, int qs, int cs, int cs2, int us,
                                               const float* __restrict__ trv,
                                               float* __restrict__ outg) {
    extern __shared__ unsigned swm[];
    uint32_t smem_u = smem_u32(swm);
    int b = blockIdx.z, tile = blockIdx.x;
    int i0 = c_TI[tile] * 64, j0 = c_TJ[tile] * 64;
    bool mirror = (i0 != j0);
    int tid = threadIdx.x;
    int warp = tid >> 5, lane = tid & 31;
    int wm = warp >> 1, wn = warp & 1, g = lane >> 2, t = lane & 3;
    float acc[2][4][4] = {};

    size_t mb = (size_t)b * CC * CC;
    run_loop64(smem_u,
               H + (size_t)ps * MATSZ + mb + (size_t)i0 * CC,
               L + (size_t)ps * MATSZ + mb + (size_t)i0 * CC,
               H + (size_t)qs * MATSZ + mb + (size_t)j0 * CC,
               L + (size_t)qs * MATSZ + mb + (size_t)j0 * CC,
               CC, CC / CHK, acc, wm, wn, lane, tid);

    __syncthreads();
    __half* M = (__half*)swm;
    __half* C1h = H + (size_t)cs * MATSZ + mb;
    __half* C1l = L + (size_t)cs * MATSZ + mb;
    __half* C2h = H + (size_t)cs2 * MATSZ + mb;
    __half* C2l = L + (size_t)cs2 * MATSZ + mb;
    const __half* Uh = H + (size_t)us * MATSZ + mb;
    const __half* Ul = L + (size_t)us * MATSZ + mb;
    const bool dual = (EPI == 3 || EPI == 4);
    float scale = (EPI == 2) ? sqrtf(trv[b]) * INVS2 : INVS2;

#pragma unroll
    for (int it = 0; it < 2; ++it)
#pragma unroll
        for (int jt = 0; jt < 4; ++jt) {
            int gi = i0 + wm * 32 + it * 16 + g;
            int gj = j0 + wn * 32 + jt * 8 + 2 * t;
            float* ca = acc[it][jt];
#pragma unroll
            for (int h = 0; h < 2; ++h) {
                int r = gi + h * 8;
                float v0 = ca[h * 2 + 0] * scale, v1 = ca[h * 2 + 1] * scale;
                if (EPI == 2) {
                    int base = r * CC - (r * (r - 1)) / 2 - r;
                    if (gj >= r) outg[(size_t)b * OUTC + base + gj] = v0;
                    if (gj + 1 >= r) outg[(size_t)b * OUTC + base + gj + 1] = v1;
                    continue;
                }
                float uv0 = 0.f, uv1 = 0.f;
                if (EPI >= 3) {
                    __half2 xh = *(const __half2*)&Uh[(size_t)r * CC + gj];
                    __half2 xl = *(const __half2*)&Ul[(size_t)r * CC + gj];
                    uv0 = (__half2float(__low2half(xh)) + __half2float(__low2half(xl))) *
                          (1.0f / SSCALE);
                    uv1 = (__half2float(__high2half(xh)) + __half2float(__high2half(xl))) *
                          (1.0f / SSCALE);
                }
                float d0 = (r == gj) ? 1.f : 0.f;
                float d1 = (r == gj + 1) ? 1.f : 0.f;
                float o10 = v0, o11 = v1, o20 = 0.f, o21 = 0.f;
                if (EPI == 3) {
                    o10 = 0.25f * v0 - 1.5f * uv0 + 2.25f * d0;
                    o11 = 0.25f * v1 - 1.5f * uv1 + 2.25f * d1;
                    o20 = 1.5f * uv0 - 0.5f * v0;
                    o21 = 1.5f * uv1 - 0.5f * v1;
                } else if (EPI == 4) {
                    o20 = 0.0625f * v0 - 0.5625f * uv0 + 1.6875f * d0;
                    o21 = 0.0625f * v1 - 0.5625f * uv1 + 1.6875f * d1;
                } else if (EPI == 5) {
                    o10 = v0 - 2.4375f * uv0 + 2.25f * d0;
                    o11 = v1 - 2.4375f * uv1 + 2.25f * d1;
                }
                unsigned hi1, lo1, hi2 = 0, lo2 = 0;
                split_pair(o10, o11, hi1, lo1);
                *(unsigned*)&C1h[(size_t)r * CC + gj] = hi1;
                *(unsigned*)&C1l[(size_t)r * CC + gj] = lo1;
                if (dual) {
                    split_pair(o20, o21, hi2, lo2);
                    *(unsigned*)&C2h[(size_t)r * CC + gj] = hi2;
                    *(unsigned*)&C2l[(size_t)r * CC + gj] = lo2;
                }
                if (mirror) {
                    int r_l = r - i0, c_l = gj - j0;
                    __half2 x = *(__half2*)&hi1;
                    M[(0 * 64 + c_l) * MP + r_l] = __low2half(x);
                    M[(0 * 64 + c_l + 1) * MP + r_l] = __high2half(x);
                    x = *(__half2*)&lo1;
                    M[(1 * 64 + c_l) * MP + r_l] = __low2half(x);
                    M[(1 * 64 + c_l + 1) * MP + r_l] = __high2half(x);
                    if (dual) {
                        x = *(__half2*)&hi2;
                        M[(2 * 64 + c_l) * MP + r_l] = __low2half(x);
                        M[(2 * 64 + c_l + 1) * MP + r_l] = __high2half(x);
                        x = *(__half2*)&lo2;
                        M[(3 * 64 + c_l) * MP + r_l] = __low2half(x);
                        M[(3 * 64 + c_l + 1) * MP + r_l] = __high2half(x);
                    }
                }
            }
        }
    if (EPI != 2 && mirror) {
        __syncthreads();
        const int NITER = dual ? 2 : 1;
#pragma unroll
        for (int u = 0; u < NITER; ++u) {
            int unit = tid + u * 128;
            int pl = unit >> 6, c_l = unit & 63;
            const uint4* srcv = (const uint4*)(M + (pl * 64 + c_l) * MP);
            __half* dstp = (pl == 0) ? C1h : (pl == 1) ? C1l : (pl == 2) ? C2h : C2l;
            uint4* dstv = (uint4*)(dstp + (size_t)(j0 + c_l) * CC + i0);
#pragma unroll
            for (int w2 = 0; w2 < 8; ++w2) dstv[w2] = srcv[w2];
        }
    }
}

// ---------------- launch ----------------
extern "C" void kernel_launch(void* const* d_in, const int* in_sizes, int n_in,
                              void* d_out, int out_size) {
    const float* x = (const float*)d_in[0];
    float* out = (float*)d_out;

    __half *H, *L, *Xh, *Xl;
    float *s, *q, *tr;
    cudaGetSymbolAddress((void**)&H, g_H);
    cudaGetSymbolAddress((void**)&L, g_L);
    cudaGetSymbolAddress((void**)&Xh, g_Xh);
    cudaGetSymbolAddress((void**)&Xl, g_Xl);
    cudaGetSymbolAddress((void**)&s, g_s);
    cudaGetSymbolAddress((void**)&q, g_q);
    cudaGetSymbolAddress((void**)&tr, g_tr);

    cudaFuncSetAttribute(gram_mma, cudaFuncAttributeMaxDynamicSharedMemorySize, SMEM64);
    cudaFuncSetAttribute(ns_pair, cudaFuncAttributeMaxDynamicSharedMemorySize, SMEM64);
    cudaFuncSetAttribute(ns64<0>, cudaFuncAttributeMaxDynamicSharedMemorySize, SMEM64);
    cudaFuncSetAttribute(ns64<2>, cudaFuncAttributeMaxDynamicSharedMemorySize, SMEM64);
    cudaFuncSetAttribute(ns64<3>, cudaFuncAttributeMaxDynamicSharedMemorySize, SMEM64);
    cudaFuncSetAttribute(ns64<4>, cudaFuncAttributeMaxDynamicSharedMemorySize, SMEM64);
    cudaFuncSetAttribute(ns64<5>, cudaFuncAttributeMaxDynamicSharedMemorySize, SMEM64);

    splitx_kernel<<<dim3(CC, BB), 256>>>(x, Xh, Xl, s, q);
    trred_kernel<<<BB, 256>>>(s, q, tr);

    dim3 g64(10, 1, BB);   // 320 CTAs
    dim3 gp(10, 2, BB);    // 640 CTAs

    // slot map (time-multiplexed): 0=a 1=A2'/p1/p2 2=y1/u2 3=u1/W2 4=W1/y3 5=R1/P2/R2
    gram_mma<<<g64, 128, SMEM64>>>(Xh, Xl, s, tr, H, L);               // a -> 0
    // u1 = a*b2^2, y1 = a*b2 via A2 = a^2
    ns64<3><<<g64, 128, SMEM64>>>(H, L, 0, 0, 1, 2, 0, tr, out);       // A2'(1), y1(2)
    ns64<0><<<g64, 128, SMEM64>>>(H, L, 0, 1, 3, 0, 0, tr, out);       // u1 = a@A2' -> 3
    // double-step 1: p1 = p(u1)
    ns64<4><<<g64, 128, SMEM64>>>(H, L, 3, 3, 4, 5, 3, tr, out);       // W1(4), R1(5)
    ns64<5><<<g64, 128, SMEM64>>>(H, L, 5, 4, 1, 0, 3, tr, out);       // p1 = R1@W1+lin -> 1
    // y3 = y1*p1 ; P2 = p1^2
    ns_pair<<<gp, 128, SMEM64>>>(H, L, 2, 1, 4, 1, 1, 5);              // y3 -> 4 ; P2 -> 5
    // u2 = u1*P2
    ns64<0><<<g64, 128, SMEM64>>>(H, L, 3, 5, 2, 0, 0, tr, out);       // u2 -> 2
    // double-step 2: p2 = p(u2)
    ns64<4><<<g64, 128, SMEM64>>>(H, L, 2, 2, 3, 5, 2, tr, out);       // W2(3), R2(5)
    ns64<5><<<g64, 128, SMEM64>>>(H, L, 5, 3, 1, 0, 2, tr, out);       // p2 -> 1
    // y5 = y3*p2, triuvec * sqrt(tr)
    ns64<2><<<g64, 128, SMEM64>>>(H, L, 4, 1, 0, 0, 0, tr, out);
}